// round 9
// baseline (speedup 1.0000x reference)
#include <cuda_runtime.h>
#include <math_constants.h>

#define B 16
#define T 32
#define WW 128
#define D 1024
#define NDBLK 64            // d-chunks for projection partials
#define DCHUNK (D / NDBLK)  // 16

// Scratch (no device allocation allowed). .bss is zero-initialized: masked-turn
// rows of g_cw are never written and stay exactly 0 across graph replays.
__device__ float g_part[2 * NDBLK * B * D];  // 8 MB
__device__ float g_q[2 * B * D];
__device__ float g_cw[B * T * D];
__device__ float g_ts[B * T];
__device__ int g_cnt[B];  // per-batch completion tickets (reset each call)

// ---------------------------------------------------------------------------
// Kernel 1: partial projections q = source @ W (W stored [indim, outdim]).
// grid = (NDBLK, 1, 2 mats) = 128 CTAs of 512 THREADS (16 warps/SM -> 2x
// latency hiding vs 256-thread CTAs). Thread halves split the batch dim:
// tid<256 -> batches 0..7, tid>=256 -> batches 8..15, same 4 columns.
// The duplicated W float4 read is served by L1/L2; DRAM reads W once.
// ---------------------------------------------------------------------------
__global__ __launch_bounds__(512) void proj_part_kernel(
    const float* __restrict__ src, const float* __restrict__ Wword,
    const float* __restrict__ Wturn) {
  int dblk = blockIdx.x;
  int mat = blockIdx.z;
  const float* __restrict__ Wm = mat ? Wturn : Wword;
  int tid = threadIdx.x;
  int b0 = (tid >> 8) * 8;       // 0 or 8
  int c4 = (tid & 255) * 4;
  int d0 = dblk * DCHUNK;

  __shared__ float s_src[DCHUNK][B];
  if (tid < DCHUNK * B) {  // 16*16 = 256
    int dl = tid >> 4, bb = tid & 15;
    s_src[dl][bb] = src[bb * D + d0 + dl];
  }
  __syncthreads();

  float4 acc[8];
#pragma unroll
  for (int bb = 0; bb < 8; bb++) acc[bb] = make_float4(0.f, 0.f, 0.f, 0.f);

#pragma unroll
  for (int dl = 0; dl < DCHUNK; dl++) {
    float4 wv = *reinterpret_cast<const float4*>(&Wm[(d0 + dl) * D + c4]);
#pragma unroll
    for (int bb = 0; bb < 8; bb++) {
      float s = s_src[dl][b0 + bb];
      acc[bb].x = fmaf(s, wv.x, acc[bb].x);
      acc[bb].y = fmaf(s, wv.y, acc[bb].y);
      acc[bb].z = fmaf(s, wv.z, acc[bb].z);
      acc[bb].w = fmaf(s, wv.w, acc[bb].w);
    }
  }

#pragma unroll
  for (int bb = 0; bb < 8; bb++) {
    float* outp = g_part + ((long)(mat * NDBLK + dblk) * B + (b0 + bb)) * D + c4;
    *reinterpret_cast<float4*>(outp) = acc[bb];
  }
}

// ---------------------------------------------------------------------------
// Kernel 2: reduce NDBLK partials -> g_q[2][B][D]; also resets g_cnt (stream-
// ordered before attn -> deterministic graph replays). grid = 128 x 256.
// ---------------------------------------------------------------------------
__global__ __launch_bounds__(256) void reduce_q_kernel() {
  if (blockIdx.x == 0 && threadIdx.x < B) g_cnt[threadIdx.x] = 0;
  int idx = blockIdx.x * 256 + threadIdx.x;  // 0..32767 over [2][16][1024]
  int mat = idx >> 14;
  int b = (idx >> 10) & 15;
  int c = idx & 1023;
  const float* bp = g_part + ((long)mat * NDBLK * B + b) * D + c;
  float s0 = 0.f, s1 = 0.f, s2 = 0.f, s3 = 0.f;
#pragma unroll
  for (int j = 0; j < NDBLK; j += 4) {
    s0 += bp[(long)(j + 0) * B * D];
    s1 += bp[(long)(j + 1) * B * D];
    s2 += bp[(long)(j + 2) * B * D];
    s3 += bp[(long)(j + 3) * B * D];
  }
  g_q[(mat * B + b) * D + c] = (s0 + s1) + (s2 + s3);
}

// ---------------------------------------------------------------------------
// Kernel 3: per-(b,t) word attention [R6-measured 2-row/iter body] + fused
// turn combine via per-batch ticket (last CTA of batch b does the combine).
// 256 threads, 8 warps; warp-private online softmax, no mainloop barriers.
// [Byte-identical to R8 — measured.]
// ---------------------------------------------------------------------------
__global__ __launch_bounds__(256) void attn_kernel(
    const float* __restrict__ bank, const int* __restrict__ lens,
    const int* __restrict__ turns, float* __restrict__ out) {
  int t = blockIdx.x, b = blockIdx.y;
  int nt = turns[b];
  if (t >= nt) return;  // masked turn: contributes exactly 0 downstream
  int len = lens[b * T + t];
  int tid = threadIdx.x, wp = tid >> 5, lane = tid & 31;

  float4 qw[8];
#pragma unroll
  for (int j = 0; j < 8; j++)
    qw[j] = *reinterpret_cast<const float4*>(g_q + b * D + j * 128 + lane * 4);

  const float* __restrict__ base = bank + (long)(b * T + t) * WW * D;

  float m = -CUDART_INF_F, ssum = 0.f;
  float4 acc[8];
#pragma unroll
  for (int j = 0; j < 8; j++) acc[j] = make_float4(0.f, 0.f, 0.f, 0.f);

  int w = wp;
#pragma unroll 1
  for (; w + 8 < len; w += 16) {  // two rows per iteration: w, w+8
    float4 r0[8], r1[8];
#pragma unroll
    for (int j = 0; j < 8; j++)
      r0[j] = *reinterpret_cast<const float4*>(base + w * D + j * 128 + lane * 4);
#pragma unroll
    for (int j = 0; j < 8; j++)
      r1[j] = *reinterpret_cast<const float4*>(base + (w + 8) * D + j * 128 + lane * 4);

    float p0 = 0.f, p1 = 0.f;
#pragma unroll
    for (int j = 0; j < 8; j++) {
      p0 = fmaf(qw[j].x, r0[j].x, fmaf(qw[j].y, r0[j].y,
           fmaf(qw[j].z, r0[j].z, fmaf(qw[j].w, r0[j].w, p0))));
      p1 = fmaf(qw[j].x, r1[j].x, fmaf(qw[j].y, r1[j].y,
           fmaf(qw[j].z, r1[j].z, fmaf(qw[j].w, r1[j].w, p1))));
    }
#pragma unroll
    for (int off = 16; off; off >>= 1) {
      p0 += __shfl_xor_sync(0xffffffffu, p0, off);
      p1 += __shfl_xor_sync(0xffffffffu, p1, off);
    }
    float mnew = fmaxf(m, fmaxf(p0, p1));
    float sc = __expf(m - mnew);        // 0 on first iteration (m = -inf)
    float e0 = __expf(p0 - mnew);
    float e1 = __expf(p1 - mnew);
    ssum = fmaf(ssum, sc, e0 + e1);
    m = mnew;
#pragma unroll
    for (int j = 0; j < 8; j++) {
      acc[j].x = fmaf(e1, r1[j].x, fmaf(e0, r0[j].x, acc[j].x * sc));
      acc[j].y = fmaf(e1, r1[j].y, fmaf(e0, r0[j].y, acc[j].y * sc));
      acc[j].z = fmaf(e1, r1[j].z, fmaf(e0, r0[j].z, acc[j].z * sc));
      acc[j].w = fmaf(e1, r1[j].w, fmaf(e0, r0[j].w, acc[j].w * sc));
    }
  }
  if (w < len) {  // tail row
    float4 r0[8];
#pragma unroll
    for (int j = 0; j < 8; j++)
      r0[j] = *reinterpret_cast<const float4*>(base + w * D + j * 128 + lane * 4);
    float p0 = 0.f;
#pragma unroll
    for (int j = 0; j < 8; j++)
      p0 = fmaf(qw[j].x, r0[j].x, fmaf(qw[j].y, r0[j].y,
           fmaf(qw[j].z, r0[j].z, fmaf(qw[j].w, r0[j].w, p0))));
#pragma unroll
    for (int off = 16; off; off >>= 1) p0 += __shfl_xor_sync(0xffffffffu, p0, off);
    float mnew = fmaxf(m, p0);
    float sc = __expf(m - mnew);
    float e0 = __expf(p0 - mnew);
    ssum = fmaf(ssum, sc, e0);
    m = mnew;
#pragma unroll
    for (int j = 0; j < 8; j++) {
      acc[j].x = fmaf(e0, r0[j].x, acc[j].x * sc);
      acc[j].y = fmaf(e0, r0[j].y, acc[j].y * sc);
      acc[j].z = fmaf(e0, r0[j].z, acc[j].z * sc);
      acc[j].w = fmaf(e0, r0[j].w, acc[j].w * sc);
    }
  }

  // ---- merge 8 warp-private (m, ssum, acc) states ----
  __shared__ float s_ms[8][2];
  __shared__ __align__(16) float s_acc[8][D];  // 32 KB
  if (lane == 0) { s_ms[wp][0] = m; s_ms[wp][1] = ssum; }
  __syncthreads();
  float M = -CUDART_INF_F;
#pragma unroll
  for (int k = 0; k < 8; k++) M = fmaxf(M, s_ms[k][0]);
  float S = 0.f;
#pragma unroll
  for (int k = 0; k < 8; k++) S += s_ms[k][1] * __expf(s_ms[k][0] - M);
  float wt = __expf(m - M);  // 0 for warps that saw no rows (m = -inf)
#pragma unroll
  for (int j = 0; j < 8; j++) {
    float4 v = make_float4(acc[j].x * wt, acc[j].y * wt, acc[j].z * wt, acc[j].w * wt);
    *reinterpret_cast<float4*>(&s_acc[wp][j * 128 + lane * 4]) = v;
  }
  __syncthreads();

  int c4 = tid * 4;
  float4 sum = make_float4(0.f, 0.f, 0.f, 0.f);
#pragma unroll
  for (int k = 0; k < 8; k++) {
    float4 v = *reinterpret_cast<const float4*>(&s_acc[k][c4]);
    sum.x += v.x; sum.y += v.y; sum.z += v.z; sum.w += v.w;
  }
  float inv = 1.f / S;
  float4 cw = make_float4(sum.x * inv, sum.y * inv, sum.z * inv, sum.w * inv);
  *reinterpret_cast<float4*>(g_cw + (b * T + t) * D + c4) = cw;

  // turn score: q_t . cw (block reduce)
  float4 qt = *reinterpret_cast<const float4*>(g_q + (B + b) * D + c4);
  float tp = fmaf(qt.x, cw.x, fmaf(qt.y, cw.y, fmaf(qt.z, cw.z, qt.w * cw.w)));
#pragma unroll
  for (int off = 16; off; off >>= 1) tp += __shfl_down_sync(0xffffffffu, tp, off);
  if (lane == 0) s_ms[wp][0] = tp;
  __syncthreads();
  if (tid == 0) {
    float v = 0.f;
#pragma unroll
    for (int k = 0; k < 8; k++) v += s_ms[k][0];
    g_ts[b * T + t] = v;
  }

  // ---- ticket: last CTA of batch b performs the turn combine ----
  __shared__ int s_last;
  __threadfence();  // release our g_cw/g_ts writes
  __syncthreads();  // all threads' stores issued before the ticket
  if (tid == 0) s_last = (atomicAdd(&g_cnt[b], 1) == nt - 1);
  __syncthreads();
  if (!s_last) return;
  __threadfence();  // acquire: observe all other CTAs' writes for batch b

  __shared__ float attw[T];
  if (tid < 32) {  // T == 32; masked turns get weight exactly 0
    float s = (tid < nt) ? g_ts[b * T + tid] : -CUDART_INF_F;
    float mx = s;
#pragma unroll
    for (int off = 16; off; off >>= 1)
      mx = fmaxf(mx, __shfl_xor_sync(0xffffffffu, mx, off));
    float e = (tid < nt) ? __expf(s - mx) : 0.f;
    float sm = e;
#pragma unroll
    for (int off = 16; off; off >>= 1)
      sm += __shfl_xor_sync(0xffffffffu, sm, off);
    attw[tid] = e / sm;
  }
  __syncthreads();

  // weighted combine over 32 turns (masked rows of g_cw are exactly 0)
  float4 o0 = make_float4(0.f, 0.f, 0.f, 0.f), o1 = o0, o2 = o0, o3 = o0;
  const float* cwb = g_cw + (long)b * T * D + c4;
#pragma unroll
  for (int tt = 0; tt < T; tt += 4) {
    float a0 = attw[tt], a1 = attw[tt + 1], a2 = attw[tt + 2], a3 = attw[tt + 3];
    float4 v0 = *reinterpret_cast<const float4*>(cwb + (long)tt * D);
    float4 v1 = *reinterpret_cast<const float4*>(cwb + (long)(tt + 1) * D);
    float4 v2 = *reinterpret_cast<const float4*>(cwb + (long)(tt + 2) * D);
    float4 v3 = *reinterpret_cast<const float4*>(cwb + (long)(tt + 3) * D);
    o0.x = fmaf(a0, v0.x, o0.x); o0.y = fmaf(a0, v0.y, o0.y);
    o0.z = fmaf(a0, v0.z, o0.z); o0.w = fmaf(a0, v0.w, o0.w);
    o1.x = fmaf(a1, v1.x, o1.x); o1.y = fmaf(a1, v1.y, o1.y);
    o1.z = fmaf(a1, v1.z, o1.z); o1.w = fmaf(a1, v1.w, o1.w);
    o2.x = fmaf(a2, v2.x, o2.x); o2.y = fmaf(a2, v2.y, o2.y);
    o2.z = fmaf(a2, v2.z, o2.z); o2.w = fmaf(a2, v2.w, o2.w);
    o3.x = fmaf(a3, v3.x, o3.x); o3.y = fmaf(a3, v3.y, o3.y);
    o3.z = fmaf(a3, v3.z, o3.z); o3.w = fmaf(a3, v3.w, o3.w);
  }
  float4 o = make_float4(o0.x + o1.x + o2.x + o3.x, o0.y + o1.y + o2.y + o3.y,
                         o0.z + o1.z + o2.z + o3.z, o0.w + o1.w + o2.w + o3.w);
  *reinterpret_cast<float4*>(out + b * D + c4) = o;
}

// ---------------------------------------------------------------------------
extern "C" void kernel_launch(void* const* d_in, const int* in_sizes, int n_in,
                              void* d_out, int out_size) {
  const float *src = nullptr, *bank = nullptr, *Wword = nullptr, *Wturn = nullptr;
  const int *lens = nullptr, *turns = nullptr;
  for (int i = 0; i < n_in; i++) {
    switch (in_sizes[i]) {
      case B * D:            src  = (const float*)d_in[i]; break;
      case B * T * WW * D:   bank = (const float*)d_in[i]; break;
      case B * T:            lens = (const int*)d_in[i];   break;
      case B:                turns = (const int*)d_in[i];  break;
      case D * D:
        if (!Wword) Wword = (const float*)d_in[i];
        else        Wturn = (const float*)d_in[i];
        break;
      default: break;
    }
  }
  proj_part_kernel<<<dim3(NDBLK, 1, 2), 512>>>(src, Wword, Wturn);
  reduce_q_kernel<<<128, 256>>>();
  attn_kernel<<<dim3(T, B), 256>>>(bank, lens, turns, (float*)d_out);
}

// round 10
// speedup vs baseline: 1.0667x; 1.0667x over previous
#include <cuda_runtime.h>
#include <math_constants.h>
#include <cstdint>

#define B 16
#define T 32
#define WW 128
#define D 1024
#define NDBLK 64            // d-chunks for projection partials
#define DCHUNK (D / NDBLK)  // 16

#define FMA_F32X2(d, a, b, c) \
  asm("fma.rn.f32x2 %0, %1, %2, %3;" : "=l"(d) : "l"(a), "l"(b), "l"(c))
#define PACK2(out, lo, hi) \
  asm("mov.b64 %0, {%1, %2};" : "=l"(out) : "f"(lo), "f"(hi))
#define UNPACK2(lo, hi, in) \
  asm("mov.b64 {%0, %1}, %2;" : "=f"(lo), "=f"(hi) : "l"(in))

// Scratch (no device allocation allowed). .bss zero-init: masked-turn rows of
// g_cw are never written and stay exactly 0 across graph replays.
__device__ float g_part[2 * NDBLK * B * D];  // 8 MB
__device__ float g_q[2 * B * D];
__device__ float g_cw[B * T * D];
__device__ float g_ts[B * T];

// ---------------------------------------------------------------------------
// Kernel 1: partial projections q = source @ W via packed fp32x2 FMAs.
// grid = (NDBLK, 1, 2 mats) = 128 CTAs, 256 threads; W read exactly once.
// smem holds src pre-packed as (s,s) pairs -> inner loop is LDS.64 + 2 FFMA2.
// ---------------------------------------------------------------------------
__global__ __launch_bounds__(256) void proj_part_kernel(
    const float* __restrict__ src, const float* __restrict__ Wword,
    const float* __restrict__ Wturn) {
  int dblk = blockIdx.x;
  int mat = blockIdx.z;
  const float* __restrict__ Wm = mat ? Wturn : Wword;
  int c4 = threadIdx.x * 4;
  int d0 = dblk * DCHUNK;

  __shared__ uint64_t s_src2[DCHUNK][B];  // (s,s) packed, 2 KB
  if (threadIdx.x < DCHUNK * B) {  // 16*16 = 256
    int dl = threadIdx.x >> 4, bb = threadIdx.x & 15;
    float v = src[bb * D + d0 + dl];
    uint64_t p; PACK2(p, v, v);
    s_src2[dl][bb] = p;
  }
  __syncthreads();

  uint64_t accA[B], accB[B];  // (x,y) and (z,w) packed accumulators
#pragma unroll
  for (int bb = 0; bb < B; bb++) { accA[bb] = 0ull; accB[bb] = 0ull; }

#pragma unroll
  for (int dl = 0; dl < DCHUNK; dl++) {
    float4 wv = *reinterpret_cast<const float4*>(&Wm[(d0 + dl) * D + c4]);
    uint64_t wxy, wzw;
    PACK2(wxy, wv.x, wv.y);
    PACK2(wzw, wv.z, wv.w);
#pragma unroll
    for (int bb = 0; bb < B; bb++) {
      uint64_t ss = s_src2[dl][bb];
      FMA_F32X2(accA[bb], wxy, ss, accA[bb]);
      FMA_F32X2(accB[bb], wzw, ss, accB[bb]);
    }
  }

#pragma unroll
  for (int bb = 0; bb < B; bb++) {
    float x, y, z, w;
    UNPACK2(x, y, accA[bb]);
    UNPACK2(z, w, accB[bb]);
    float* outp = g_part + ((long)(mat * NDBLK + dblk) * B + bb) * D + c4;
    *reinterpret_cast<float4*>(outp) = make_float4(x, y, z, w);
  }
}

// ---------------------------------------------------------------------------
// Kernel 2: reduce NDBLK partials -> g_q[2][B][D]. grid = 128 x 256.
// ---------------------------------------------------------------------------
__global__ __launch_bounds__(256) void reduce_q_kernel() {
  int idx = blockIdx.x * 256 + threadIdx.x;  // 0..32767 over [2][16][1024]
  int mat = idx >> 14;
  int b = (idx >> 10) & 15;
  int c = idx & 1023;
  const float* bp = g_part + ((long)mat * NDBLK * B + b) * D + c;
  float s0 = 0.f, s1 = 0.f, s2 = 0.f, s3 = 0.f;
#pragma unroll
  for (int j = 0; j < NDBLK; j += 4) {
    s0 += bp[(long)(j + 0) * B * D];
    s1 += bp[(long)(j + 1) * B * D];
    s2 += bp[(long)(j + 2) * B * D];
    s3 += bp[(long)(j + 3) * B * D];
  }
  g_q[(mat * B + b) * D + c] = (s0 + s1) + (s2 + s3);
}

// ---------------------------------------------------------------------------
// Kernel 3: per-(b,t) word attention [R6-measured, verbatim]. 256 threads,
// 8 warps; warp-private online softmax, 2 rows/iter, no mainloop barriers.
// ---------------------------------------------------------------------------
__global__ __launch_bounds__(256) void attn_kernel(
    const float* __restrict__ bank, const int* __restrict__ lens,
    const int* __restrict__ turns) {
  int t = blockIdx.x, b = blockIdx.y;
  if (t >= turns[b]) return;  // masked turn: contributes exactly 0 downstream
  int len = lens[b * T + t];
  int tid = threadIdx.x, wp = tid >> 5, lane = tid & 31;

  float4 qw[8];
#pragma unroll
  for (int j = 0; j < 8; j++)
    qw[j] = *reinterpret_cast<const float4*>(g_q + b * D + j * 128 + lane * 4);

  const float* __restrict__ base = bank + (long)(b * T + t) * WW * D;

  float m = -CUDART_INF_F, ssum = 0.f;
  float4 acc[8];
#pragma unroll
  for (int j = 0; j < 8; j++) acc[j] = make_float4(0.f, 0.f, 0.f, 0.f);

  int w = wp;
#pragma unroll 1
  for (; w + 8 < len; w += 16) {  // two rows per iteration: w, w+8
    float4 r0[8], r1[8];
#pragma unroll
    for (int j = 0; j < 8; j++)
      r0[j] = *reinterpret_cast<const float4*>(base + w * D + j * 128 + lane * 4);
#pragma unroll
    for (int j = 0; j < 8; j++)
      r1[j] = *reinterpret_cast<const float4*>(base + (w + 8) * D + j * 128 + lane * 4);

    float p0 = 0.f, p1 = 0.f;
#pragma unroll
    for (int j = 0; j < 8; j++) {
      p0 = fmaf(qw[j].x, r0[j].x, fmaf(qw[j].y, r0[j].y,
           fmaf(qw[j].z, r0[j].z, fmaf(qw[j].w, r0[j].w, p0))));
      p1 = fmaf(qw[j].x, r1[j].x, fmaf(qw[j].y, r1[j].y,
           fmaf(qw[j].z, r1[j].z, fmaf(qw[j].w, r1[j].w, p1))));
    }
#pragma unroll
    for (int off = 16; off; off >>= 1) {
      p0 += __shfl_xor_sync(0xffffffffu, p0, off);
      p1 += __shfl_xor_sync(0xffffffffu, p1, off);
    }
    float mnew = fmaxf(m, fmaxf(p0, p1));
    float sc = __expf(m - mnew);        // 0 on first iteration (m = -inf)
    float e0 = __expf(p0 - mnew);
    float e1 = __expf(p1 - mnew);
    ssum = fmaf(ssum, sc, e0 + e1);
    m = mnew;
#pragma unroll
    for (int j = 0; j < 8; j++) {
      acc[j].x = fmaf(e1, r1[j].x, fmaf(e0, r0[j].x, acc[j].x * sc));
      acc[j].y = fmaf(e1, r1[j].y, fmaf(e0, r0[j].y, acc[j].y * sc));
      acc[j].z = fmaf(e1, r1[j].z, fmaf(e0, r0[j].z, acc[j].z * sc));
      acc[j].w = fmaf(e1, r1[j].w, fmaf(e0, r0[j].w, acc[j].w * sc));
    }
  }
  if (w < len) {  // tail row
    float4 r0[8];
#pragma unroll
    for (int j = 0; j < 8; j++)
      r0[j] = *reinterpret_cast<const float4*>(base + w * D + j * 128 + lane * 4);
    float p0 = 0.f;
#pragma unroll
    for (int j = 0; j < 8; j++)
      p0 = fmaf(qw[j].x, r0[j].x, fmaf(qw[j].y, r0[j].y,
           fmaf(qw[j].z, r0[j].z, fmaf(qw[j].w, r0[j].w, p0))));
#pragma unroll
    for (int off = 16; off; off >>= 1) p0 += __shfl_xor_sync(0xffffffffu, p0, off);
    float mnew = fmaxf(m, p0);
    float sc = __expf(m - mnew);
    float e0 = __expf(p0 - mnew);
    ssum = fmaf(ssum, sc, e0);
    m = mnew;
#pragma unroll
    for (int j = 0; j < 8; j++) {
      acc[j].x = fmaf(e0, r0[j].x, acc[j].x * sc);
      acc[j].y = fmaf(e0, r0[j].y, acc[j].y * sc);
      acc[j].z = fmaf(e0, r0[j].z, acc[j].z * sc);
      acc[j].w = fmaf(e0, r0[j].w, acc[j].w * sc);
    }
  }

  // ---- merge 8 warp-private (m, ssum, acc) states ----
  __shared__ float s_ms[8][2];
  __shared__ __align__(16) float s_acc[8][D];  // 32 KB
  if (lane == 0) { s_ms[wp][0] = m; s_ms[wp][1] = ssum; }
  __syncthreads();
  float M = -CUDART_INF_F;
#pragma unroll
  for (int k = 0; k < 8; k++) M = fmaxf(M, s_ms[k][0]);
  float S = 0.f;
#pragma unroll
  for (int k = 0; k < 8; k++) S += s_ms[k][1] * __expf(s_ms[k][0] - M);
  float wt = __expf(m - M);  // 0 for warps that saw no rows (m = -inf)
#pragma unroll
  for (int j = 0; j < 8; j++) {
    float4 v = make_float4(acc[j].x * wt, acc[j].y * wt, acc[j].z * wt, acc[j].w * wt);
    *reinterpret_cast<float4*>(&s_acc[wp][j * 128 + lane * 4]) = v;
  }
  __syncthreads();

  int c4 = tid * 4;
  float4 sum = make_float4(0.f, 0.f, 0.f, 0.f);
#pragma unroll
  for (int k = 0; k < 8; k++) {
    float4 v = *reinterpret_cast<const float4*>(&s_acc[k][c4]);
    sum.x += v.x; sum.y += v.y; sum.z += v.z; sum.w += v.w;
  }
  float inv = 1.f / S;
  float4 cw = make_float4(sum.x * inv, sum.y * inv, sum.z * inv, sum.w * inv);
  *reinterpret_cast<float4*>(g_cw + (b * T + t) * D + c4) = cw;

  // turn score: q_t . cw (block reduce)
  float4 qt = *reinterpret_cast<const float4*>(g_q + (B + b) * D + c4);
  float tp = fmaf(qt.x, cw.x, fmaf(qt.y, cw.y, fmaf(qt.z, cw.z, qt.w * cw.w)));
#pragma unroll
  for (int off = 16; off; off >>= 1) tp += __shfl_down_sync(0xffffffffu, tp, off);
  if (lane == 0) s_ms[wp][0] = tp;
  __syncthreads();
  if (tid == 0) {
    float v = 0.f;
#pragma unroll
    for (int k = 0; k < 8; k++) v += s_ms[k][0];
    g_ts[b * T + t] = v;
  }
}

// ---------------------------------------------------------------------------
// Kernel 4: turn softmax + combine [R5/R6-measured]. grid = (8, B) = 128
// CTAs, 256 threads. Masked turns: weight exactly 0, zero g_cw rows.
// ---------------------------------------------------------------------------
__global__ __launch_bounds__(256) void combine_kernel(
    const int* __restrict__ turns, float* __restrict__ out) {
  int b = blockIdx.y;
  int chunk = blockIdx.x;  // 128 cols = 32 float4
  int nt = turns[b];
  int tid = threadIdx.x;
  __shared__ float attw[T];
  __shared__ __align__(16) float s_red[8][128];
  if (tid < 32) {  // T == 32
    float s = (tid < nt) ? g_ts[b * T + tid] : -CUDART_INF_F;
    float mx = s;
#pragma unroll
    for (int off = 16; off; off >>= 1)
      mx = fmaxf(mx, __shfl_xor_sync(0xffffffffu, mx, off));
    float e = (tid < nt) ? __expf(s - mx) : 0.f;
    float sm = e;
#pragma unroll
    for (int off = 16; off; off >>= 1)
      sm += __shfl_xor_sync(0xffffffffu, sm, off);
    attw[tid] = e / sm;
  }
  __syncthreads();

  int c = tid & 31;   // float4 index within the 128-col chunk
  int tg = tid >> 5;  // 0..7 -> turns tg*4 .. tg*4+3
  int c4 = chunk * 128 + c * 4;
  float4 acc = make_float4(0.f, 0.f, 0.f, 0.f);
#pragma unroll
  for (int i = 0; i < 4; i++) {
    int t = tg * 4 + i;
    float a = attw[t];
    float4 cw = *reinterpret_cast<const float4*>(g_cw + (b * T + t) * D + c4);
    acc.x = fmaf(a, cw.x, acc.x);
    acc.y = fmaf(a, cw.y, acc.y);
    acc.z = fmaf(a, cw.z, acc.z);
    acc.w = fmaf(a, cw.w, acc.w);
  }
  *reinterpret_cast<float4*>(&s_red[tg][c * 4]) = acc;
  __syncthreads();
  if (tid < 32) {
    float4 o = make_float4(0.f, 0.f, 0.f, 0.f);
#pragma unroll
    for (int k = 0; k < 8; k++) {
      float4 v = *reinterpret_cast<const float4*>(&s_red[k][tid * 4]);
      o.x += v.x; o.y += v.y; o.z += v.z; o.w += v.w;
    }
    *reinterpret_cast<float4*>(out + b * D + chunk * 128 + tid * 4) = o;
  }
}

// ---------------------------------------------------------------------------
extern "C" void kernel_launch(void* const* d_in, const int* in_sizes, int n_in,
                              void* d_out, int out_size) {
  const float *src = nullptr, *bank = nullptr, *Wword = nullptr, *Wturn = nullptr;
  const int *lens = nullptr, *turns = nullptr;
  for (int i = 0; i < n_in; i++) {
    switch (in_sizes[i]) {
      case B * D:            src  = (const float*)d_in[i]; break;
      case B * T * WW * D:   bank = (const float*)d_in[i]; break;
      case B * T:            lens = (const int*)d_in[i];   break;
      case B:                turns = (const int*)d_in[i];  break;
      case D * D:
        if (!Wword) Wword = (const float*)d_in[i];
        else        Wturn = (const float*)d_in[i];
        break;
      default: break;
    }
  }
  proj_part_kernel<<<dim3(NDBLK, 1, 2), 256>>>(src, Wword, Wturn);
  reduce_q_kernel<<<128, 256>>>();
  attn_kernel<<<dim3(T, B), 256>>>(bank, lens, turns);
  combine_kernel<<<dim3(8, B), 256>>>(turns, (float*)d_out);
}

// round 11
// speedup vs baseline: 1.1404x; 1.0691x over previous
#include <cuda_runtime.h>
#include <math_constants.h>
#include <cstdint>

#define B 16
#define T 32
#define WW 128
#define D 1024
#define NDBLK 64            // d-chunks for projection partials
#define DCHUNK (D / NDBLK)  // 16

#define FMA_F32X2(d, a, b, c) \
  asm("fma.rn.f32x2 %0, %1, %2, %3;" : "=l"(d) : "l"(a), "l"(b), "l"(c))
#define PACK2(out, lo, hi) \
  asm("mov.b64 %0, {%1, %2};" : "=l"(out) : "f"(lo), "f"(hi))
#define UNPACK2(lo, hi, in) \
  asm("mov.b64 {%0, %1}, %2;" : "=f"(lo), "=f"(hi) : "l"(in))

// Scratch (no device allocation allowed). .bss zero-init: masked-turn rows of
// g_cw are never written and stay exactly 0 across graph replays.
__device__ float g_part[2 * NDBLK * B * D];  // 8 MB
__device__ float g_q[2 * B * D];
__device__ float g_cw[B * T * D];
__device__ float g_ts[B * T];

// ---------------------------------------------------------------------------
// Kernel 1: partial projections q = source @ W via packed fp32x2 FMAs.
// grid = (NDBLK, 1, 2 mats) = 128 CTAs, 256 threads; W read exactly once.
// [R10-measured]
// ---------------------------------------------------------------------------
__global__ __launch_bounds__(256) void proj_part_kernel(
    const float* __restrict__ src, const float* __restrict__ Wword,
    const float* __restrict__ Wturn) {
  int dblk = blockIdx.x;
  int mat = blockIdx.z;
  const float* __restrict__ Wm = mat ? Wturn : Wword;
  int c4 = threadIdx.x * 4;
  int d0 = dblk * DCHUNK;

  __shared__ uint64_t s_src2[DCHUNK][B];  // (s,s) packed, 2 KB
  if (threadIdx.x < DCHUNK * B) {  // 16*16 = 256
    int dl = threadIdx.x >> 4, bb = threadIdx.x & 15;
    float v = src[bb * D + d0 + dl];
    uint64_t p; PACK2(p, v, v);
    s_src2[dl][bb] = p;
  }
  __syncthreads();

  uint64_t accA[B], accB[B];  // (x,y) and (z,w) packed accumulators
#pragma unroll
  for (int bb = 0; bb < B; bb++) { accA[bb] = 0ull; accB[bb] = 0ull; }

#pragma unroll
  for (int dl = 0; dl < DCHUNK; dl++) {
    float4 wv = *reinterpret_cast<const float4*>(&Wm[(d0 + dl) * D + c4]);
    uint64_t wxy, wzw;
    PACK2(wxy, wv.x, wv.y);
    PACK2(wzw, wv.z, wv.w);
#pragma unroll
    for (int bb = 0; bb < B; bb++) {
      uint64_t ss = s_src2[dl][bb];
      FMA_F32X2(accA[bb], wxy, ss, accA[bb]);
      FMA_F32X2(accB[bb], wzw, ss, accB[bb]);
    }
  }

#pragma unroll
  for (int bb = 0; bb < B; bb++) {
    float x, y, z, w;
    UNPACK2(x, y, accA[bb]);
    UNPACK2(z, w, accB[bb]);
    float* outp = g_part + ((long)(mat * NDBLK + dblk) * B + bb) * D + c4;
    *reinterpret_cast<float4*>(outp) = make_float4(x, y, z, w);
  }
}

// ---------------------------------------------------------------------------
// Kernel 2: reduce NDBLK partials -> g_q[2][B][D]. grid = 128 x 256.
// [R10-measured]
// ---------------------------------------------------------------------------
__global__ __launch_bounds__(256) void reduce_q_kernel() {
  int idx = blockIdx.x * 256 + threadIdx.x;  // 0..32767 over [2][16][1024]
  int mat = idx >> 14;
  int b = (idx >> 10) & 15;
  int c = idx & 1023;
  const float* bp = g_part + ((long)mat * NDBLK * B + b) * D + c;
  float s0 = 0.f, s1 = 0.f, s2 = 0.f, s3 = 0.f;
#pragma unroll
  for (int j = 0; j < NDBLK; j += 4) {
    s0 += bp[(long)(j + 0) * B * D];
    s1 += bp[(long)(j + 1) * B * D];
    s2 += bp[(long)(j + 2) * B * D];
    s3 += bp[(long)(j + 3) * B * D];
  }
  g_q[(mat * B + b) * D + c] = (s0 + s1) + (s2 + s3);
}

// ---------------------------------------------------------------------------
// Kernel 3: per-(b,t) word attention [R6-measured, verbatim]. 256 threads,
// 8 warps; warp-private online softmax, 2 rows/iter, no mainloop barriers.
// ---------------------------------------------------------------------------
__global__ __launch_bounds__(256) void attn_kernel(
    const float* __restrict__ bank, const int* __restrict__ lens,
    const int* __restrict__ turns) {
  int t = blockIdx.x, b = blockIdx.y;
  if (t >= turns[b]) return;  // masked turn: contributes exactly 0 downstream
  int len = lens[b * T + t];
  int tid = threadIdx.x, wp = tid >> 5, lane = tid & 31;

  float4 qw[8];
#pragma unroll
  for (int j = 0; j < 8; j++)
    qw[j] = *reinterpret_cast<const float4*>(g_q + b * D + j * 128 + lane * 4);

  const float* __restrict__ base = bank + (long)(b * T + t) * WW * D;

  float m = -CUDART_INF_F, ssum = 0.f;
  float4 acc[8];
#pragma unroll
  for (int j = 0; j < 8; j++) acc[j] = make_float4(0.f, 0.f, 0.f, 0.f);

  int w = wp;
#pragma unroll 1
  for (; w + 8 < len; w += 16) {  // two rows per iteration: w, w+8
    float4 r0[8], r1[8];
#pragma unroll
    for (int j = 0; j < 8; j++)
      r0[j] = *reinterpret_cast<const float4*>(base + w * D + j * 128 + lane * 4);
#pragma unroll
    for (int j = 0; j < 8; j++)
      r1[j] = *reinterpret_cast<const float4*>(base + (w + 8) * D + j * 128 + lane * 4);

    float p0 = 0.f, p1 = 0.f;
#pragma unroll
    for (int j = 0; j < 8; j++) {
      p0 = fmaf(qw[j].x, r0[j].x, fmaf(qw[j].y, r0[j].y,
           fmaf(qw[j].z, r0[j].z, fmaf(qw[j].w, r0[j].w, p0))));
      p1 = fmaf(qw[j].x, r1[j].x, fmaf(qw[j].y, r1[j].y,
           fmaf(qw[j].z, r1[j].z, fmaf(qw[j].w, r1[j].w, p1))));
    }
#pragma unroll
    for (int off = 16; off; off >>= 1) {
      p0 += __shfl_xor_sync(0xffffffffu, p0, off);
      p1 += __shfl_xor_sync(0xffffffffu, p1, off);
    }
    float mnew = fmaxf(m, fmaxf(p0, p1));
    float sc = __expf(m - mnew);        // 0 on first iteration (m = -inf)
    float e0 = __expf(p0 - mnew);
    float e1 = __expf(p1 - mnew);
    ssum = fmaf(ssum, sc, e0 + e1);
    m = mnew;
#pragma unroll
    for (int j = 0; j < 8; j++) {
      acc[j].x = fmaf(e1, r1[j].x, fmaf(e0, r0[j].x, acc[j].x * sc));
      acc[j].y = fmaf(e1, r1[j].y, fmaf(e0, r0[j].y, acc[j].y * sc));
      acc[j].z = fmaf(e1, r1[j].z, fmaf(e0, r0[j].z, acc[j].z * sc));
      acc[j].w = fmaf(e1, r1[j].w, fmaf(e0, r0[j].w, acc[j].w * sc));
    }
  }
  if (w < len) {  // tail row
    float4 r0[8];
#pragma unroll
    for (int j = 0; j < 8; j++)
      r0[j] = *reinterpret_cast<const float4*>(base + w * D + j * 128 + lane * 4);
    float p0 = 0.f;
#pragma unroll
    for (int j = 0; j < 8; j++)
      p0 = fmaf(qw[j].x, r0[j].x, fmaf(qw[j].y, r0[j].y,
           fmaf(qw[j].z, r0[j].z, fmaf(qw[j].w, r0[j].w, p0))));
#pragma unroll
    for (int off = 16; off; off >>= 1) p0 += __shfl_xor_sync(0xffffffffu, p0, off);
    float mnew = fmaxf(m, p0);
    float sc = __expf(m - mnew);
    float e0 = __expf(p0 - mnew);
    ssum = fmaf(ssum, sc, e0);
    m = mnew;
#pragma unroll
    for (int j = 0; j < 8; j++) {
      acc[j].x = fmaf(e0, r0[j].x, acc[j].x * sc);
      acc[j].y = fmaf(e0, r0[j].y, acc[j].y * sc);
      acc[j].z = fmaf(e0, r0[j].z, acc[j].z * sc);
      acc[j].w = fmaf(e0, r0[j].w, acc[j].w * sc);
    }
  }

  // ---- merge 8 warp-private (m, ssum, acc) states ----
  __shared__ float s_ms[8][2];
  __shared__ __align__(16) float s_acc[8][D];  // 32 KB
  if (lane == 0) { s_ms[wp][0] = m; s_ms[wp][1] = ssum; }
  __syncthreads();
  float M = -CUDART_INF_F;
#pragma unroll
  for (int k = 0; k < 8; k++) M = fmaxf(M, s_ms[k][0]);
  float S = 0.f;
#pragma unroll
  for (int k = 0; k < 8; k++) S += s_ms[k][1] * __expf(s_ms[k][0] - M);
  float wt = __expf(m - M);  // 0 for warps that saw no rows (m = -inf)
#pragma unroll
  for (int j = 0; j < 8; j++) {
    float4 v = make_float4(acc[j].x * wt, acc[j].y * wt, acc[j].z * wt, acc[j].w * wt);
    *reinterpret_cast<float4*>(&s_acc[wp][j * 128 + lane * 4]) = v;
  }
  __syncthreads();

  int c4 = tid * 4;
  float4 sum = make_float4(0.f, 0.f, 0.f, 0.f);
#pragma unroll
  for (int k = 0; k < 8; k++) {
    float4 v = *reinterpret_cast<const float4*>(&s_acc[k][c4]);
    sum.x += v.x; sum.y += v.y; sum.z += v.z; sum.w += v.w;
  }
  float inv = 1.f / S;
  float4 cw = make_float4(sum.x * inv, sum.y * inv, sum.z * inv, sum.w * inv);
  *reinterpret_cast<float4*>(g_cw + (b * T + t) * D + c4) = cw;

  // turn score: q_t . cw (block reduce)
  float4 qt = *reinterpret_cast<const float4*>(g_q + (B + b) * D + c4);
  float tp = fmaf(qt.x, cw.x, fmaf(qt.y, cw.y, fmaf(qt.z, cw.z, qt.w * cw.w)));
#pragma unroll
  for (int off = 16; off; off >>= 1) tp += __shfl_down_sync(0xffffffffu, tp, off);
  if (lane == 0) s_ms[wp][0] = tp;
  __syncthreads();
  if (tid == 0) {
    float v = 0.f;
#pragma unroll
    for (int k = 0; k < 8; k++) v += s_ms[k][0];
    g_ts[b * T + t] = v;
  }
}

// ---------------------------------------------------------------------------
// Kernel 4: turn softmax + combine, LOADS-FIRST layout. grid = (16, B) =
// 256 CTAs, 256 threads. tid -> (tg = tid>>4 of 2 turns, float4 col c).
// The two g_cw loads issue at kernel entry; warp 0 computes the softmax
// while they are in flight; weights applied after one barrier.
// Masked turns: weight exactly 0, g_cw rows exactly 0.
// ---------------------------------------------------------------------------
__global__ __launch_bounds__(256) void combine_kernel(
    const int* __restrict__ turns, float* __restrict__ out) {
  int b = blockIdx.y;
  int chunk = blockIdx.x;  // 64 cols = 16 float4
  int tid = threadIdx.x;
  int c = tid & 15;        // float4 index within chunk
  int tg = tid >> 4;       // 0..15 -> turns tg*2, tg*2+1
  int c4 = chunk * 64 + c * 4;
  int t0 = tg * 2, t1 = tg * 2 + 1;

  // Issue value loads FIRST — independent of the softmax.
  float4 v0 = *reinterpret_cast<const float4*>(g_cw + (b * T + t0) * D + c4);
  float4 v1 = *reinterpret_cast<const float4*>(g_cw + (b * T + t1) * D + c4);

  __shared__ float attw[T];
  __shared__ __align__(16) float s_red[16][64];
  if (tid < 32) {  // warp 0 softmax, overlapped with the loads above
    int nt = turns[b];
    float s = (tid < nt) ? g_ts[b * T + tid] : -CUDART_INF_F;
    float mx = s;
#pragma unroll
    for (int off = 16; off; off >>= 1)
      mx = fmaxf(mx, __shfl_xor_sync(0xffffffffu, mx, off));
    float e = (tid < nt) ? __expf(s - mx) : 0.f;
    float sm = e;
#pragma unroll
    for (int off = 16; off; off >>= 1)
      sm += __shfl_xor_sync(0xffffffffu, sm, off);
    attw[tid] = e / sm;
  }
  __syncthreads();

  float a0 = attw[t0], a1 = attw[t1];
  float4 acc;
  acc.x = fmaf(a0, v0.x, a1 * v1.x);
  acc.y = fmaf(a0, v0.y, a1 * v1.y);
  acc.z = fmaf(a0, v0.z, a1 * v1.z);
  acc.w = fmaf(a0, v0.w, a1 * v1.w);
  *reinterpret_cast<float4*>(&s_red[tg][c * 4]) = acc;
  __syncthreads();

  if (tid < 16) {  // reduce 16 turn-groups for one float4 each
    float4 o = make_float4(0.f, 0.f, 0.f, 0.f);
#pragma unroll
    for (int k = 0; k < 16; k++) {
      float4 v = *reinterpret_cast<const float4*>(&s_red[k][tid * 4]);
      o.x += v.x; o.y += v.y; o.z += v.z; o.w += v.w;
    }
    *reinterpret_cast<float4*>(out + b * D + chunk * 64 + tid * 4) = o;
  }
}

// ---------------------------------------------------------------------------
extern "C" void kernel_launch(void* const* d_in, const int* in_sizes, int n_in,
                              void* d_out, int out_size) {
  const float *src = nullptr, *bank = nullptr, *Wword = nullptr, *Wturn = nullptr;
  const int *lens = nullptr, *turns = nullptr;
  for (int i = 0; i < n_in; i++) {
    switch (in_sizes[i]) {
      case B * D:            src  = (const float*)d_in[i]; break;
      case B * T * WW * D:   bank = (const float*)d_in[i]; break;
      case B * T:            lens = (const int*)d_in[i];   break;
      case B:                turns = (const int*)d_in[i];  break;
      case D * D:
        if (!Wword) Wword = (const float*)d_in[i];
        else        Wturn = (const float*)d_in[i];
        break;
      default: break;
    }
  }
  proj_part_kernel<<<dim3(NDBLK, 1, 2), 256>>>(src, Wword, Wturn);
  reduce_q_kernel<<<128, 256>>>();
  attn_kernel<<<dim3(T, B), 256>>>(bank, lens, turns);
  combine_kernel<<<dim3(16, B), 256>>>(turns, (float*)d_out);
}